// round 4
// baseline (speedup 1.0000x reference)
#include <cuda_runtime.h>
#include <cstdint>

// Fixed problem sizes (from reference): N=100000 nodes, E=1600000 edges, d=128.
#define NMAX 100000
#define EMAX 1600000
#define D    128

// Scratch (device globals — no allocations allowed)
__device__ float g_dinv[NMAX];          // deg -> rsqrt(deg)
__device__ float g_norm[EMAX];          // dinv[src]*dinv[dst], reused both layers
__device__ float g_h[(size_t)NMAX * D]; // GEMM output (messages)
__device__ float g_a[(size_t)NMAX * D]; // aggregation buffer

// ---------------------------------------------------------------------------
// degree / norm precompute
// ---------------------------------------------------------------------------
__global__ void deg_init(int n) {
    int i = blockIdx.x * blockDim.x + threadIdx.x;
    if (i < n) g_dinv[i] = 1.0f;  // self-loop
}

__global__ void deg_hist(const int* __restrict__ dst, int e) {
    int i = blockIdx.x * blockDim.x + threadIdx.x;
    if (i < e) atomicAdd(&g_dinv[dst[i]], 1.0f);
}

__global__ void deg_finish(int n) {
    int i = blockIdx.x * blockDim.x + threadIdx.x;
    if (i < n) g_dinv[i] = rsqrtf(g_dinv[i]);
}

__global__ void norm_compute(const int* __restrict__ src, const int* __restrict__ dst, int e) {
    int i = blockIdx.x * blockDim.x + threadIdx.x;
    if (i < e) g_norm[i] = g_dinv[src[i]] * g_dinv[dst[i]];
}

// ---------------------------------------------------------------------------
// GEMM: C[N,128] = A[N,128] @ W[128,128]
// Block: 256 threads, 64 rows. W (64KB) + A-tile (32KB) in dynamic shared.
// Thread layout: lane = tid&31 -> 4 consecutive cols; tid>>5 -> row slot,
// each thread does 8 rows x 4 cols = 32 accumulators.
// ---------------------------------------------------------------------------
__global__ void gemm128(const float* __restrict__ A, const float* __restrict__ W,
                        float* __restrict__ C, int n) {
    extern __shared__ float sm[];
    float* sW = sm;             // 128*128
    float* sA = sm + 128 * 128; // 64*128

    int tid = threadIdx.x;
    // load W (4096 float4, 16 per thread)
    const float4* W4 = reinterpret_cast<const float4*>(W);
    float4* sW4 = reinterpret_cast<float4*>(sW);
#pragma unroll
    for (int i = 0; i < 16; i++) sW4[tid + 256 * i] = W4[tid + 256 * i];

    int row0 = blockIdx.x * 64;
    int nrows = n - row0; if (nrows > 64) nrows = 64;
    const float4* A4 = reinterpret_cast<const float4*>(A + (size_t)row0 * D);
    float4* sA4 = reinterpret_cast<float4*>(sA);
    for (int i = tid; i < nrows * 32; i += 256) sA4[i] = A4[i];
    __syncthreads();

    int lane = tid & 31;
    int rbase = tid >> 5;  // 0..7

    float acc[8][4];
#pragma unroll
    for (int r = 0; r < 8; r++) {
        acc[r][0] = 0.f; acc[r][1] = 0.f; acc[r][2] = 0.f; acc[r][3] = 0.f;
    }

#pragma unroll 8
    for (int k = 0; k < 128; k++) {
        float4 w = sW4[k * 32 + lane];
#pragma unroll
        for (int r = 0; r < 8; r++) {
            float a = sA[(rbase + r * 8) * 128 + k];  // warp-uniform: LDS broadcast
            acc[r][0] += a * w.x;
            acc[r][1] += a * w.y;
            acc[r][2] += a * w.z;
            acc[r][3] += a * w.w;
        }
    }

    float4* C4 = reinterpret_cast<float4*>(C);
#pragma unroll
    for (int r = 0; r < 8; r++) {
        int rr = rbase + r * 8;
        if (rr < nrows) {
            float4 v; v.x = acc[r][0]; v.y = acc[r][1]; v.z = acc[r][2]; v.w = acc[r][3];
            C4[(size_t)(row0 + rr) * 32 + lane] = v;
        }
    }
}

// ---------------------------------------------------------------------------
// Aggregation init: g_a[i] = g_h[i] * dinv[i]^2  (self-loop contribution)
// ---------------------------------------------------------------------------
__global__ void agg_init(int n) {
    int i = blockIdx.x * blockDim.x + threadIdx.x;  // over n*32 float4
    if (i >= n * 32) return;
    const float4* h4 = reinterpret_cast<const float4*>(g_h);
    float4* a4 = reinterpret_cast<float4*>(g_a);
    float d = g_dinv[i >> 5];
    float s = d * d;
    float4 v = h4[i];
    v.x *= s; v.y *= s; v.z *= s; v.w *= s;
    a4[i] = v;
}

// ---------------------------------------------------------------------------
// Edge aggregation: one warp per edge; lane handles 4 floats (float4).
// g_a[dst] += g_h[src] * norm  via red.global.add.v4.f32 (sm_90+).
// ---------------------------------------------------------------------------
__global__ void agg_edges(const int* __restrict__ src, const int* __restrict__ dst, int e) {
    int w = (blockIdx.x * blockDim.x + threadIdx.x) >> 5;
    int lane = threadIdx.x & 31;
    if (w >= e) return;
    int s = __ldg(src + w);
    int d = __ldg(dst + w);
    float nm = g_norm[w];
    const float4* hv = reinterpret_cast<const float4*>(g_h) + (size_t)s * 32 + lane;
    float4 v = *hv;
    float4* av = reinterpret_cast<float4*>(g_a) + (size_t)d * 32 + lane;
    asm volatile("red.global.add.v4.f32 [%0], {%1,%2,%3,%4};"
                 :: "l"(av), "f"(v.x * nm), "f"(v.y * nm), "f"(v.z * nm), "f"(v.w * nm)
                 : "memory");
}

// ---------------------------------------------------------------------------
// bias (+optional relu) in place on g_a
// ---------------------------------------------------------------------------
__global__ void bias_act(const float* __restrict__ b, int n, int relu) {
    int i = blockIdx.x * blockDim.x + threadIdx.x;  // over n*32 float4
    if (i >= n * 32) return;
    const float4* b4 = reinterpret_cast<const float4*>(b);
    float4* a4 = reinterpret_cast<float4*>(g_a);
    float4 bb = b4[i & 31];
    float4 v = a4[i];
    v.x += bb.x; v.y += bb.y; v.z += bb.z; v.w += bb.w;
    if (relu) {
        v.x = fmaxf(v.x, 0.f); v.y = fmaxf(v.y, 0.f);
        v.z = fmaxf(v.z, 0.f); v.w = fmaxf(v.w, 0.f);
    }
    a4[i] = v;
}

// ---------------------------------------------------------------------------
// Output GEMM: out[N,40] = g_a[N,128] @ Wout[128,40] + bout
// Thread per output element; Wout + bout in static shared.
// ---------------------------------------------------------------------------
__global__ void gemm_out(const float* __restrict__ W, const float* __restrict__ b,
                         float* __restrict__ C, int n) {
    __shared__ float sW[128 * 40];
    __shared__ float sb[40];
    int tid = threadIdx.x;
    for (int i = tid; i < 128 * 40; i += blockDim.x) sW[i] = W[i];
    if (tid < 40) sb[tid] = b[tid];
    __syncthreads();

    int idx = blockIdx.x * blockDim.x + tid;
    if (idx >= n * 40) return;
    int row = idx / 40;
    int j = idx - row * 40;
    const float4* a4 = reinterpret_cast<const float4*>(g_a) + (size_t)row * 32;
    float acc = sb[j];
#pragma unroll 8
    for (int k4 = 0; k4 < 32; k4++) {
        float4 av = a4[k4];  // warp mostly reads same row -> L1 broadcast
        int kb = k4 * 4;
        acc += av.x * sW[(kb + 0) * 40 + j];
        acc += av.y * sW[(kb + 1) * 40 + j];
        acc += av.z * sW[(kb + 2) * 40 + j];
        acc += av.w * sW[(kb + 3) * 40 + j];
    }
    C[idx] = acc;
}

// ---------------------------------------------------------------------------
// launch
// ---------------------------------------------------------------------------
extern "C" void kernel_launch(void* const* d_in, const int* in_sizes, int n_in,
                              void* d_out, int out_size) {
    const float* x    = (const float*)d_in[0];
    const int*   ei   = (const int*)d_in[1];
    const float* W1   = (const float*)d_in[2];
    const float* b1   = (const float*)d_in[3];
    const float* W2   = (const float*)d_in[4];
    const float* b2   = (const float*)d_in[5];
    const float* Wout = (const float*)d_in[6];
    const float* bout = (const float*)d_in[7];
    float* out = (float*)d_out;

    int n = in_sizes[0] / D;       // 100000
    int e = in_sizes[1] / 2;       // 1600000
    const int* src = ei;
    const int* dst = ei + e;

    static bool attr_set = false;
    if (!attr_set) {
        cudaFuncSetAttribute(gemm128, cudaFuncAttributeMaxDynamicSharedMemorySize,
                             (128 * 128 + 64 * 128) * (int)sizeof(float));
        attr_set = true;
    }
    const int smem_gemm = (128 * 128 + 64 * 128) * (int)sizeof(float);

    float* hbuf = nullptr;  // resolved via device symbols inside kernels
    (void)hbuf;

    int tb = 256;
    // 1) degrees -> dinv -> edge norms (reused by both layers)
    deg_init<<<(n + tb - 1) / tb, tb>>>(n);
    deg_hist<<<(e + tb - 1) / tb, tb>>>(dst, e);
    deg_finish<<<(n + tb - 1) / tb, tb>>>(n);
    norm_compute<<<(e + tb - 1) / tb, tb>>>(src, dst, e);

    int gemm_blocks = (n + 63) / 64;
    int vec_blocks  = (n * 32 + tb - 1) / tb;
    int edge_blocks = (e + 7) / 8;  // 8 warps (edges) per 256-thread block

    // ---- layer 1: h = x@W1 ; a = Ahat h ; a = relu(a + b1) ----
    {
        float* g_h_ptr; cudaGetSymbolAddress((void**)&g_h_ptr, g_h);
        gemm128<<<gemm_blocks, tb, smem_gemm>>>(x, W1, g_h_ptr, n);
    }
    agg_init<<<vec_blocks, tb>>>(n);
    agg_edges<<<edge_blocks, tb>>>(src, dst, e);
    bias_act<<<vec_blocks, tb>>>(b1, n, 1);

    // ---- layer 2: h = a@W2 ; a = Ahat h ; a = a + b2 ----
    {
        float* g_h_ptr; cudaGetSymbolAddress((void**)&g_h_ptr, g_h);
        float* g_a_ptr; cudaGetSymbolAddress((void**)&g_a_ptr, g_a);
        gemm128<<<gemm_blocks, tb, smem_gemm>>>(g_a_ptr, W2, g_h_ptr, n);
    }
    agg_init<<<vec_blocks, tb>>>(n);
    agg_edges<<<edge_blocks, tb>>>(src, dst, e);
    bias_act<<<vec_blocks, tb>>>(b2, n, 0);

    // ---- output: out = a@Wout + bout ----
    gemm_out<<<(n * 40 + tb - 1) / tb, tb>>>(Wout, bout, out, n);
}